// round 8
// baseline (speedup 1.0000x reference)
#include <cuda_runtime.h>
#include <cstdint>

// Problem constants
#define NODES   32768            // B*N = 8*4096
#define NEDGE   524288
#define HDIM    128
#define RNUM    8
#define LNUM    2
#define KTOT    (HDIM + RNUM*HDIM)   // 1152
#define N8      (NODES * RNUM)       // 262144 CSR bins (dst, rel)

// ---- projection GEMM tile params (unchanged from R4) ----
#define CHUNK   32
#define PADK    36
#define TILEF   (128 * PADK)
#define GEMM_SMEM (4 * TILEF * 4)    // 73728 B

// ---- fused layer kernel params ----
#define FK_PAD  68                   // smem row stride (floats), conflict-free frags
#define FK_ASZ  (256 * FK_PAD)       // A buffer floats (M-tile 256 x 64)
#define FK_BSZ  (128 * FK_PAD)       // B buffer floats (128 n x 64 k)
#define FUSED_SMEM ((2 * FK_ASZ + 2 * FK_BSZ) * 4)   // 208896 B
#define NCHUNK  18                   // 2 self halves + 8 rel x 2 halves

// ---------------- scratch (static device globals; no allocation) ------------
__device__ float g_x0[(size_t)NODES * HDIM];
__device__ float g_x1[(size_t)NODES * HDIM];
__device__ float g_Wc[LNUM][(size_t)HDIM * KTOT];            // [l][n*KTOT + k]
__device__ int   g_rowptr8[N8 + 1];
__device__ int   g_cursor8[N8];
__device__ int   g_cnt8[N8];
__device__ int   g_bsum[256];
__device__ float g_invdeg[NODES];
__device__ int   g_edges8[NEDGE];                            // src only (type implicit)

__device__ __forceinline__ uint32_t f2tf32(float v) {
    uint32_t r; asm("cvt.rna.tf32.f32 %0, %1;" : "=r"(r) : "f"(v)); return r;
}
__device__ __forceinline__ void mma_tf32(float* d, const uint32_t* a,
                                         uint32_t b0, uint32_t b1) {
    asm volatile(
        "mma.sync.aligned.m16n8k8.row.col.f32.tf32.tf32.f32 "
        "{%0,%1,%2,%3}, {%4,%5,%6,%7}, {%8,%9}, {%0,%1,%2,%3};"
        : "+f"(d[0]), "+f"(d[1]), "+f"(d[2]), "+f"(d[3])
        : "r"(a[0]), "r"(a[1]), "r"(a[2]), "r"(a[3]), "r"(b0), "r"(b1));
}

// ---------------- CSR build over (dst, rel) bins ----------------------------
__global__ void zero_cnt8_kernel() {
    int i = blockIdx.x * blockDim.x + threadIdx.x;
    if (i < N8) g_cnt8[i] = 0;
}
__global__ void hist8_kernel(const int* __restrict__ dst,
                             const int* __restrict__ et) {
    int i = blockIdx.x * blockDim.x + threadIdx.x;
    if (i < NEDGE) atomicAdd(&g_cnt8[dst[i] * RNUM + et[i]], 1);
}
// scan1: per-block (1024 elems) exclusive scan + block sums
__global__ void scan1_kernel() {
    __shared__ int sh[1024];
    int t = threadIdx.x;
    int i = blockIdx.x * 1024 + t;
    int v = g_cnt8[i];
    sh[t] = v;
    __syncthreads();
    for (int off = 1; off < 1024; off <<= 1) {
        int u = (t >= off) ? sh[t - off] : 0;
        __syncthreads();
        sh[t] += u;
        __syncthreads();
    }
    g_rowptr8[i] = sh[t] - v;         // block-local exclusive
    if (t == 1023) g_bsum[blockIdx.x] = sh[1023];
}
// scan2: exclusive scan of 256 block sums
__global__ void scan2_kernel() {
    __shared__ int sh[256];
    int t = threadIdx.x;
    int v = g_bsum[t];
    sh[t] = v;
    __syncthreads();
    for (int off = 1; off < 256; off <<= 1) {
        int u = (t >= off) ? sh[t - off] : 0;
        __syncthreads();
        sh[t] += u;
        __syncthreads();
    }
    g_bsum[t] = sh[t] - v;
}
// scan3: add block offsets, init cursor, finalize sentinel
__global__ void scan3_kernel() {
    int t = threadIdx.x;
    int i = blockIdx.x * 1024 + t;
    int rp = g_rowptr8[i] + g_bsum[blockIdx.x];
    g_rowptr8[i] = rp;
    g_cursor8[i] = rp;
    if (i == N8 - 1) g_rowptr8[N8] = NEDGE;
}
__global__ void invdeg_kernel() {
    int i = blockIdx.x * blockDim.x + threadIdx.x;
    if (i < NODES) {
        int d = g_rowptr8[(i + 1) * RNUM] - g_rowptr8[i * RNUM];
        g_invdeg[i] = 1.0f / (float)max(d, 1);
    }
}
__global__ void scatter8_kernel(const int* __restrict__ src,
                                const int* __restrict__ dst,
                                const int* __restrict__ et) {
    int i = blockIdx.x * blockDim.x + threadIdx.x;
    if (i < NEDGE) {
        int pos = atomicAdd(&g_cursor8[dst[i] * RNUM + et[i]], 1);
        g_edges8[pos] = src[i];
    }
}

// ------- weight prep: Wc[l][n*KTOT + k] = [self_W[l,n,:] | rel_W[l,r,n,:]] ---
__global__ void prep_w_kernel(const float* __restrict__ sW,
                              const float* __restrict__ rW) {
    const int total = LNUM * HDIM * KTOT;
    for (int idx = blockIdx.x * blockDim.x + threadIdx.x; idx < total;
         idx += gridDim.x * blockDim.x) {
        int l  = idx / (HDIM * KTOT);
        int jj = idx % (HDIM * KTOT);
        int n  = jj / KTOT, k = jj % KTOT;
        float v;
        if (k < HDIM) {
            v = sW[((size_t)l * HDIM + n) * HDIM + k];
        } else {
            int kk = k - HDIM;
            int r = kk >> 7, h = kk & 127;
            v = rW[(((size_t)(l * RNUM + r) * HDIM) + n) * HDIM + h];
        }
        g_Wc[l][jj] = v;
    }
}

// ---------------- embedding -------------------------------------------------
__global__ void embed_kernel(const int* __restrict__ cid,
                             const int* __restrict__ kid,
                             const float* __restrict__ ce,
                             const float* __restrict__ ke) {
    int i = blockIdx.x * blockDim.x + threadIdx.x;
    int v = i >> 5, j = i & 31;
    float4 a = ((const float4*)ce)[(size_t)cid[v] * 32 + j];
    float4 b = ((const float4*)ke)[(size_t)kid[v] * 32 + j];
    float4 o;
    o.x = a.x + b.x; o.y = a.y + b.y; o.z = a.z + b.z; o.w = a.w + b.w;
    ((float4*)g_x0)[(size_t)v * 32 + j] = o;
}

// ====== projection GEMM (R4 kernel, A1 only): x1 = x0 @ pW^T + pb ===========
__global__ __launch_bounds__(256, 2)
void mma_gemm_kernel(const float* __restrict__ A1, int K,
                     const float* __restrict__ Bw,
                     const float* __restrict__ bias, float* __restrict__ out) {
    extern __shared__ float sm[];
    float* Abuf = sm;
    float* Bbuf = sm + 2 * TILEF;

    int tid = threadIdx.x, wid = tid >> 5, lane = tid & 31;
    int m0 = blockIdx.x * 128;
    int wr = wid & 3, wc = wid >> 2;
    int g = lane >> 2, tg = lane & 3;

    float acc[2][8][4];
#pragma unroll
    for (int mt = 0; mt < 2; mt++)
#pragma unroll
        for (int nt = 0; nt < 8; nt++)
#pragma unroll
            for (int r = 0; r < 4; r++) acc[mt][nt][r] = 0.f;

    const int NC = K / CHUNK;
    float4 ra[4], rb[4];

    auto ldglobal = [&](int c) {
        int kbase = c * CHUNK;
#pragma unroll
        for (int i = 0; i < 4; i++) {
            int idx = i * 256 + tid;
            int m = idx >> 3, k4 = idx & 7;
            ra[i] = *(const float4*)&A1[(size_t)(m0 + m) * K + kbase + k4 * 4];
            rb[i] = *(const float4*)&Bw[(size_t)m * K + kbase + k4 * 4];
        }
    };
    auto stsmem = [&](int b) {
        float* Ad = Abuf + b * TILEF;
        float* Bd = Bbuf + b * TILEF;
#pragma unroll
        for (int i = 0; i < 4; i++) {
            int idx = i * 256 + tid;
            int m = idx >> 3, k4 = idx & 7;
            float4 a, w;
            a.x = __uint_as_float(f2tf32(ra[i].x));
            a.y = __uint_as_float(f2tf32(ra[i].y));
            a.z = __uint_as_float(f2tf32(ra[i].z));
            a.w = __uint_as_float(f2tf32(ra[i].w));
            w.x = __uint_as_float(f2tf32(rb[i].x));
            w.y = __uint_as_float(f2tf32(rb[i].y));
            w.z = __uint_as_float(f2tf32(rb[i].z));
            w.w = __uint_as_float(f2tf32(rb[i].w));
            *(float4*)&Ad[m * PADK + k4 * 4] = a;
            *(float4*)&Bd[m * PADK + k4 * 4] = w;
        }
    };
    auto compute = [&](int b) {
        const float* A = Abuf + b * TILEF;
        const float* Bs = Bbuf + b * TILEF;
#pragma unroll
        for (int ks = 0; ks < 4; ks++) {
            uint32_t a[2][4];
#pragma unroll
            for (int mt = 0; mt < 2; mt++) {
                const float* ap = A + (wr * 32 + mt * 16 + g) * PADK + ks * 8 + tg;
                a[mt][0] = __float_as_uint(ap[0]);
                a[mt][1] = __float_as_uint(ap[8 * PADK]);
                a[mt][2] = __float_as_uint(ap[4]);
                a[mt][3] = __float_as_uint(ap[8 * PADK + 4]);
            }
#pragma unroll
            for (int nt = 0; nt < 8; nt++) {
                const float* bp = Bs + (wc * 64 + nt * 8 + g) * PADK + ks * 8 + tg;
                uint32_t b0 = __float_as_uint(bp[0]);
                uint32_t b1 = __float_as_uint(bp[4]);
                mma_tf32(acc[0][nt], a[0], b0, b1);
                mma_tf32(acc[1][nt], a[1], b0, b1);
            }
        }
    };

    ldglobal(0);
    stsmem(0);
    __syncthreads();
    for (int c = 0; c < NC; c++) {
        int b = c & 1;
        if (c + 1 < NC) ldglobal(c + 1);
        compute(b);
        if (c + 1 < NC) stsmem(b ^ 1);
        __syncthreads();
    }

#pragma unroll
    for (int mt = 0; mt < 2; mt++) {
        int rb0 = m0 + wr * 32 + mt * 16 + g;
#pragma unroll
        for (int nt = 0; nt < 8; nt++) {
            int n = wc * 64 + nt * 8 + tg * 2;
            float b0 = bias[n], b1 = bias[n + 1];
            float2 o0 = make_float2(acc[mt][nt][0] + b0, acc[mt][nt][1] + b1);
            float2 o1 = make_float2(acc[mt][nt][2] + b0, acc[mt][nt][3] + b1);
            *(float2*)&out[(size_t)rb0 * 128 + n] = o0;
            *(float2*)&out[(size_t)(rb0 + 8) * 128 + n] = o1;
        }
    }
}

// ====== fused layer: out = relu( [x | agg_r(x)] @ Wc^T + bias ) [* mask] ====
// M-tile 256 per CTA, 512 threads (16 warps: 8 M x 2 N), N=128.
// K = 1152 processed as 18 chunks of 64:
//   c=0,1   : self features x (two 64-halves), direct copy
//   c>=2    : (r = (c-2)>>1, h = (c-2)&1): A rows generated by on-the-fly
//             gather-sum of x[src] over type-r edges, scaled by 1/deg.
__global__ __launch_bounds__(512, 1)
void fused_layer_kernel(const float* __restrict__ x,
                        const float* __restrict__ Wc,
                        const float* __restrict__ bias,
                        const int* __restrict__ mask,
                        float* __restrict__ out) {
    extern __shared__ float sm[];
    float* Ab = sm;                    // [2][FK_ASZ]
    float* Bb = sm + 2 * FK_ASZ;       // [2][FK_BSZ]

    int tid = threadIdx.x, wid = tid >> 5, lane = tid & 31;
    int m0 = blockIdx.x * 256;
    int wr = wid & 7, wcn = wid >> 3;   // MMA: rows wr*32, cols wcn*64
    int g = lane >> 2, tg = lane & 3;
    int hw = lane >> 4, l16 = lane & 15;  // gather: half-warp per dst

    float acc[2][8][4];
#pragma unroll
    for (int mt = 0; mt < 2; mt++)
#pragma unroll
        for (int nt = 0; nt < 8; nt++)
#pragma unroll
            for (int r = 0; r < 4; r++) acc[mt][nt][r] = 0.f;

    auto build = [&](int c, int b) {
        float* Ad = Ab + b * FK_ASZ;
        if (c < 2) {
            int h = c;
#pragma unroll
            for (int i = 0; i < 8; i++) {
                int idx = i * 512 + tid;          // 4096 = 256 rows x 16 f4
                int m = idx >> 4, k4 = idx & 15;
                float4 a = *(const float4*)&x[(size_t)(m0 + m) * 128 + h * 64 + k4 * 4];
                float4 t;
                t.x = __uint_as_float(f2tf32(a.x));
                t.y = __uint_as_float(f2tf32(a.y));
                t.z = __uint_as_float(f2tf32(a.z));
                t.w = __uint_as_float(f2tf32(a.w));
                *(float4*)&Ad[m * FK_PAD + k4 * 4] = t;
            }
        } else {
            int r = (c - 2) >> 1, h = (c - 2) & 1;
            int coff = h * 64 + l16 * 4;
#pragma unroll 1
            for (int j = 0; j < 8; j++) {
                int vloc = wid * 16 + j * 2 + hw;
                int vg = m0 + vloc;
                int e0 = g_rowptr8[vg * RNUM + r];
                int e1 = g_rowptr8[vg * RNUM + r + 1];
                float4 a0 = make_float4(0.f, 0.f, 0.f, 0.f);
                float4 a1 = make_float4(0.f, 0.f, 0.f, 0.f);
                int i = e0;
                for (; i + 1 < e1; i += 2) {
                    int s0 = g_edges8[i], s1 = g_edges8[i + 1];
                    float4 v0 = *(const float4*)&x[(size_t)s0 * 128 + coff];
                    float4 v1 = *(const float4*)&x[(size_t)s1 * 128 + coff];
                    a0.x += v0.x; a0.y += v0.y; a0.z += v0.z; a0.w += v0.w;
                    a1.x += v1.x; a1.y += v1.y; a1.z += v1.z; a1.w += v1.w;
                }
                if (i < e1) {
                    int s0 = g_edges8[i];
                    float4 v0 = *(const float4*)&x[(size_t)s0 * 128 + coff];
                    a0.x += v0.x; a0.y += v0.y; a0.z += v0.z; a0.w += v0.w;
                }
                float inv = g_invdeg[vg];
                float4 t;
                t.x = __uint_as_float(f2tf32((a0.x + a1.x) * inv));
                t.y = __uint_as_float(f2tf32((a0.y + a1.y) * inv));
                t.z = __uint_as_float(f2tf32((a0.z + a1.z) * inv));
                t.w = __uint_as_float(f2tf32((a0.w + a1.w) * inv));
                *(float4*)&Ad[vloc * FK_PAD + l16 * 4] = t;
            }
        }
        // B chunk: 128 n x 64 k
        float* Bd = Bb + b * FK_BSZ;
#pragma unroll
        for (int i = 0; i < 4; i++) {
            int idx = i * 512 + tid;              // 2048 = 128 x 16
            int n = idx >> 4, k4 = idx & 15;
            float4 w = *(const float4*)&Wc[(size_t)n * KTOT + c * 64 + k4 * 4];
            float4 t;
            t.x = __uint_as_float(f2tf32(w.x));
            t.y = __uint_as_float(f2tf32(w.y));
            t.z = __uint_as_float(f2tf32(w.z));
            t.w = __uint_as_float(f2tf32(w.w));
            *(float4*)&Bd[n * FK_PAD + k4 * 4] = t;
        }
    };

    auto domma = [&](int b) {
        const float* A = Ab + b * FK_ASZ;
        const float* Bs = Bb + b * FK_BSZ;
#pragma unroll
        for (int ks = 0; ks < 8; ks++) {
            uint32_t a[2][4];
#pragma unroll
            for (int mt = 0; mt < 2; mt++) {
                const float* ap = A + (wr * 32 + mt * 16 + g) * FK_PAD + ks * 8 + tg;
                a[mt][0] = __float_as_uint(ap[0]);
                a[mt][1] = __float_as_uint(ap[8 * FK_PAD]);
                a[mt][2] = __float_as_uint(ap[4]);
                a[mt][3] = __float_as_uint(ap[8 * FK_PAD + 4]);
            }
#pragma unroll
            for (int nt = 0; nt < 8; nt++) {
                const float* bp = Bs + (wcn * 64 + nt * 8 + g) * FK_PAD + ks * 8 + tg;
                uint32_t b0 = __float_as_uint(bp[0]);
                uint32_t b1 = __float_as_uint(bp[4]);
                mma_tf32(acc[0][nt], a[0], b0, b1);
                mma_tf32(acc[1][nt], a[1], b0, b1);
            }
        }
    };

    build(0, 0);
    __syncthreads();
    for (int c = 0; c < NCHUNK; c++) {
        int b = c & 1;
        if (c + 1 < NCHUNK) build(c + 1, b ^ 1);
        domma(b);
        __syncthreads();
    }

    // epilogue: + bias, relu, optional mask
#pragma unroll
    for (int mt = 0; mt < 2; mt++) {
        int rb0 = m0 + wr * 32 + mt * 16 + g;     // rows rb0, rb0+8
        float mk0 = 1.0f, mk1 = 1.0f;
        if (mask) {
            mk0 = mask[rb0] ? 1.0f : 0.0f;
            mk1 = mask[rb0 + 8] ? 1.0f : 0.0f;
        }
#pragma unroll
        for (int nt = 0; nt < 8; nt++) {
            int n = wcn * 64 + nt * 8 + tg * 2;
            float b0 = bias[n], b1 = bias[n + 1];
            float v00 = fmaxf(acc[0][nt][0] + b0, 0.f) * mk0;
            float v01 = fmaxf(acc[0][nt][1] + b1, 0.f) * mk0;
            float v10 = fmaxf(acc[0][nt][2] + b0, 0.f) * mk1;
            float v11 = fmaxf(acc[0][nt][3] + b1, 0.f) * mk1;
            // mt index folded: use current mt's acc
            v00 = fmaxf(acc[mt][nt][0] + b0, 0.f) * mk0;
            v01 = fmaxf(acc[mt][nt][1] + b1, 0.f) * mk0;
            v10 = fmaxf(acc[mt][nt][2] + b0, 0.f) * mk1;
            v11 = fmaxf(acc[mt][nt][3] + b1, 0.f) * mk1;
            *(float2*)&out[(size_t)rb0 * 128 + n] = make_float2(v00, v01);
            *(float2*)&out[(size_t)(rb0 + 8) * 128 + n] = make_float2(v10, v11);
        }
    }
}

// ---------------- launch ----------------------------------------------------
extern "C" void kernel_launch(void* const* d_in, const int* in_sizes, int n_in,
                              void* d_out, int out_size) {
    const int*   cid  = (const int*)  d_in[0];
    const int*   kid  = (const int*)  d_in[1];
    const int*   mask = (const int*)  d_in[2];
    const int*   eidx = (const int*)  d_in[3];
    const int*   et   = (const int*)  d_in[4];
    const float* ce   = (const float*)d_in[5];
    const float* ke   = (const float*)d_in[6];
    const float* pW   = (const float*)d_in[7];
    const float* pb   = (const float*)d_in[8];
    const float* sW   = (const float*)d_in[9];
    const float* sb   = (const float*)d_in[10];
    const float* rW   = (const float*)d_in[11];
    float* out = (float*)d_out;

    const int* esrc = eidx;
    const int* edst = eidx + NEDGE;

    float *x0p, *x1p, *Wcp;
    cudaGetSymbolAddress((void**)&x0p, g_x0);
    cudaGetSymbolAddress((void**)&x1p, g_x1);
    cudaGetSymbolAddress((void**)&Wcp, (const void*)g_Wc);

    cudaFuncSetAttribute(mma_gemm_kernel,
                         cudaFuncAttributeMaxDynamicSharedMemorySize, GEMM_SMEM);
    cudaFuncSetAttribute(fused_layer_kernel,
                         cudaFuncAttributeMaxDynamicSharedMemorySize, FUSED_SMEM);

    // 1) CSR build over (dst, rel)
    zero_cnt8_kernel<<<N8 / 256, 256>>>();
    hist8_kernel<<<NEDGE / 256, 256>>>(edst, et);
    scan1_kernel<<<256, 1024>>>();
    scan2_kernel<<<1, 256>>>();
    scan3_kernel<<<256, 1024>>>();
    invdeg_kernel<<<NODES / 256, 256>>>();
    scatter8_kernel<<<NEDGE / 256, 256>>>(esrc, edst, et);

    // 2) weights + embedding
    prep_w_kernel<<<1152, 256>>>(sW, rW);
    embed_kernel<<<(NODES * 32) / 256, 256>>>(cid, kid, ce, ke);

    // 3) projection: x1 = x0 @ proj_W^T + pb
    mma_gemm_kernel<<<NODES / 128, 256, GEMM_SMEM>>>(x0p, HDIM, pW, pb, x1p);

    // 4) layer 0 (fused agg + GEMM) -> x0
    fused_layer_kernel<<<NODES / 256, 512, FUSED_SMEM>>>(
        x1p, Wcp, sb, nullptr, x0p);

    // 5) layer 1 (fused) -> output with mask
    fused_layer_kernel<<<NODES / 256, 512, FUSED_SMEM>>>(
        x0p, Wcp + (size_t)HDIM * KTOT, sb + HDIM, mask, out);
}

// round 9
// speedup vs baseline: 1.4181x; 1.4181x over previous
#include <cuda_runtime.h>
#include <cstdint>

// Problem constants
#define NODES   32768            // B*N = 8*4096
#define NEDGE   524288
#define HDIM    128
#define RNUM    8
#define LNUM    2
#define KTOT    (HDIM + RNUM*HDIM)   // 1152

// ---- GEMM tile params: 128x128 block, CHUNK=32, 3-stage cp.async ----
#define CHUNK   32
#define PADK    36
#define STAGEF  (128 * PADK)               // floats per A (or B) stage
#define NSTAGE  3
#define GEMM_SMEM (2 * NSTAGE * STAGEF * 4)  // 110592 B

// ---------------- scratch (static device globals; no allocation) ------------
__device__ float g_x0[(size_t)NODES * HDIM];
__device__ float g_x1[(size_t)NODES * HDIM];
__device__ float g_S [(size_t)NODES * RNUM * HDIM];          // 134 MB
__device__ float g_Wc[LNUM][(size_t)HDIM * KTOT];            // [l][n*KTOT + k]
__device__ float g_Wp[HDIM * HDIM];
__device__ int   g_rowptr[NODES + 1];
__device__ int   g_cursor[NODES];
__device__ float g_invdeg[NODES];
__device__ int   g_edges[NEDGE];                             // src | type<<16
__device__ int   g_cnt[NODES];

__device__ __forceinline__ uint32_t f2tf32(float v) {
    uint32_t r; asm("cvt.rna.tf32.f32 %0, %1;" : "=r"(r) : "f"(v)); return r;
}
__device__ __forceinline__ float rtf(float v) {
    return __uint_as_float(f2tf32(v));
}
__device__ __forceinline__ void mma_tf32(float* d, const uint32_t* a,
                                         uint32_t b0, uint32_t b1) {
    asm volatile(
        "mma.sync.aligned.m16n8k8.row.col.f32.tf32.tf32.f32 "
        "{%0,%1,%2,%3}, {%4,%5,%6,%7}, {%8,%9}, {%0,%1,%2,%3};"
        : "+f"(d[0]), "+f"(d[1]), "+f"(d[2]), "+f"(d[3])
        : "r"(a[0]), "r"(a[1]), "r"(a[2]), "r"(a[3]), "r"(b0), "r"(b1));
}
__device__ __forceinline__ uint32_t smem_u32(const void* p) {
    uint32_t a;
    asm("{ .reg .u64 t; cvta.to.shared.u64 t, %1; cvt.u32.u64 %0, t; }"
        : "=r"(a) : "l"(p));
    return a;
}
__device__ __forceinline__ void cp16(uint32_t dst, const float* src) {
    asm volatile("cp.async.cg.shared.global [%0], [%1], 16;"
                 :: "r"(dst), "l"(src) : "memory");
}
__device__ __forceinline__ void cp_commit() {
    asm volatile("cp.async.commit_group;" ::: "memory");
}
__device__ __forceinline__ void cp_wait2() {
    asm volatile("cp.async.wait_group 2;" ::: "memory");
}

// ---------------- CSR build (per dst) ---------------------------------------
__global__ void zero_cnt_kernel() {
    int i = blockIdx.x * blockDim.x + threadIdx.x;
    if (i < NODES) g_cnt[i] = 0;
}
__global__ void hist_kernel(const int* __restrict__ dst) {
    int i = blockIdx.x * blockDim.x + threadIdx.x;
    if (i < NEDGE) atomicAdd(&g_cnt[dst[i]], 1);
}
__global__ void scan_kernel() {
    __shared__ int sh[1024];
    int t = threadIdx.x;
    int base = t * 32;
    int local[32];
    int sum = 0;
#pragma unroll
    for (int i = 0; i < 32; i++) { local[i] = g_cnt[base + i]; sum += local[i]; }
    sh[t] = sum;
    __syncthreads();
    for (int off = 1; off < 1024; off <<= 1) {
        int v = (t >= off) ? sh[t - off] : 0;
        __syncthreads();
        sh[t] += v;
        __syncthreads();
    }
    int run = sh[t] - sum;
#pragma unroll
    for (int i = 0; i < 32; i++) {
        g_rowptr[base + i] = run;
        g_cursor[base + i] = run;
        g_invdeg[base + i] = 1.0f / (float)max(local[i], 1);
        run += local[i];
    }
    if (t == 1023) g_rowptr[NODES] = run;
}
__global__ void scatter_kernel(const int* __restrict__ src,
                               const int* __restrict__ dst,
                               const int* __restrict__ et) {
    int i = blockIdx.x * blockDim.x + threadIdx.x;
    if (i < NEDGE) {
        int d = dst[i];
        int pos = atomicAdd(&g_cursor[d], 1);
        g_edges[pos] = (src[i] & 0xFFFF) | (et[i] << 16);
    }
}

// ------- weight prep (tf32-rounded): Wc = [self | rel], Wp = proj_W ---------
__global__ void prep_w_kernel(const float* __restrict__ pW,
                              const float* __restrict__ sW,
                              const float* __restrict__ rW) {
    const int total = HDIM * HDIM + LNUM * HDIM * KTOT;
    for (int idx = blockIdx.x * blockDim.x + threadIdx.x; idx < total;
         idx += gridDim.x * blockDim.x) {
        if (idx < HDIM * HDIM) {
            g_Wp[idx] = rtf(pW[idx]);            // [g][h] as-is (B is N x K)
        } else {
            int j  = idx - HDIM * HDIM;
            int l  = j / (HDIM * KTOT);
            int jj = j % (HDIM * KTOT);
            int n  = jj / KTOT, k = jj % KTOT;
            float v;
            if (k < HDIM) {
                v = sW[((size_t)l * HDIM + n) * HDIM + k];
            } else {
                int kk = k - HDIM;
                int r = kk >> 7, h = kk & 127;
                v = rW[(((size_t)(l * RNUM + r) * HDIM) + n) * HDIM + h];
            }
            g_Wc[l][jj] = rtf(v);
        }
    }
}

// ---------------- embedding (tf32-rounded) ----------------------------------
__global__ void embed_kernel(const int* __restrict__ cid,
                             const int* __restrict__ kid,
                             const float* __restrict__ ce,
                             const float* __restrict__ ke) {
    int i = blockIdx.x * blockDim.x + threadIdx.x;
    int v = i >> 5, j = i & 31;
    float4 a = ((const float4*)ce)[(size_t)cid[v] * 32 + j];
    float4 b = ((const float4*)ke)[(size_t)kid[v] * 32 + j];
    float4 o;
    o.x = rtf(a.x + b.x); o.y = rtf(a.y + b.y);
    o.z = rtf(a.z + b.z); o.w = rtf(a.w + b.w);
    ((float4*)g_x0)[(size_t)v * 32 + j] = o;
}

// ---------------- aggregation: one warp per dst node (S tf32-rounded) -------
__global__ void agg_kernel(const float* __restrict__ x) {
    int warp = (blockIdx.x * blockDim.x + threadIdx.x) >> 5;
    int lane = threadIdx.x & 31;
    int v = warp;
    int s = g_rowptr[v], e = g_rowptr[v + 1];
    float4 acc[RNUM];
#pragma unroll
    for (int r = 0; r < RNUM; r++) acc[r] = make_float4(0.f, 0.f, 0.f, 0.f);
    const float4* x4 = (const float4*)x;
    for (int i = s; i < e; i++) {
        int p   = g_edges[i];
        int src = p & 0xFFFF;
        int r   = p >> 16;
        float4 xv = x4[(size_t)src * 32 + lane];
        switch (r) {
            case 0: acc[0].x += xv.x; acc[0].y += xv.y; acc[0].z += xv.z; acc[0].w += xv.w; break;
            case 1: acc[1].x += xv.x; acc[1].y += xv.y; acc[1].z += xv.z; acc[1].w += xv.w; break;
            case 2: acc[2].x += xv.x; acc[2].y += xv.y; acc[2].z += xv.z; acc[2].w += xv.w; break;
            case 3: acc[3].x += xv.x; acc[3].y += xv.y; acc[3].z += xv.z; acc[3].w += xv.w; break;
            case 4: acc[4].x += xv.x; acc[4].y += xv.y; acc[4].z += xv.z; acc[4].w += xv.w; break;
            case 5: acc[5].x += xv.x; acc[5].y += xv.y; acc[5].z += xv.z; acc[5].w += xv.w; break;
            case 6: acc[6].x += xv.x; acc[6].y += xv.y; acc[6].z += xv.z; acc[6].w += xv.w; break;
            default: acc[7].x += xv.x; acc[7].y += xv.y; acc[7].z += xv.z; acc[7].w += xv.w; break;
        }
    }
    float inv = g_invdeg[v];
    float4* S4 = (float4*)g_S;
#pragma unroll
    for (int r = 0; r < RNUM; r++) {
        float4 o;
        o.x = rtf(acc[r].x * inv); o.y = rtf(acc[r].y * inv);
        o.z = rtf(acc[r].z * inv); o.w = rtf(acc[r].w * inv);
        S4[((size_t)v * RNUM + r) * 32 + lane] = o;
    }
}

// ====== tf32 mma GEMM w/ cp.async 3-stage: out = act(A_cat@B^T+bias) ========
// A_cat rows: cols [0,K1) from A1 (lda=K1), [K1,K) from A2 (lda=K-K1).
// B: [128 n][K k] K-major, pre-rounded tf32. All inputs pre-rounded.
// round_out: round stored values to tf32 (for tensors feeding later MMAs).
__global__ __launch_bounds__(256, 2)
void mma_gemm_kernel(const float* __restrict__ A1, const float* __restrict__ A2,
                     int K1, int K, const float* __restrict__ Bw,
                     const float* __restrict__ bias, const int* __restrict__ mask,
                     int relu, int round_out, float* __restrict__ out) {
    extern __shared__ float sm[];
    float* Abuf = sm;                      // [NSTAGE][STAGEF]
    float* Bbuf = sm + NSTAGE * STAGEF;    // [NSTAGE][STAGEF]
    uint32_t Abase = smem_u32(Abuf);
    uint32_t Bbase = smem_u32(Bbuf);

    int tid = threadIdx.x, wid = tid >> 5, lane = tid & 31;
    int m0 = blockIdx.x * 128;
    int wr = wid & 3, wc = wid >> 2;
    int g = lane >> 2, tg = lane & 3;

    float acc[2][8][4];
#pragma unroll
    for (int mt = 0; mt < 2; mt++)
#pragma unroll
        for (int nt = 0; nt < 8; nt++)
#pragma unroll
            for (int r = 0; r < 4; r++) acc[mt][nt][r] = 0.f;

    const int NC = K / CHUNK;

    auto issue = [&](int c) {
        if (c < NC) {
            int kbase = c * CHUNK;
            const float* Aq; int lda, kb;
            if (kbase < K1) { Aq = A1; lda = K1;     kb = kbase; }
            else            { Aq = A2; lda = K - K1; kb = kbase - K1; }
            int st = c % NSTAGE;
            uint32_t Ad = Abase + st * STAGEF * 4;
            uint32_t Bd = Bbase + st * STAGEF * 4;
#pragma unroll
            for (int i = 0; i < 4; i++) {
                int idx = i * 256 + tid;          // 1024 f4 per tile
                int m = idx >> 3, k4 = idx & 7;
                uint32_t so = (uint32_t)(m * PADK + k4 * 4) * 4;
                cp16(Ad + so, &Aq[(size_t)(m0 + m) * lda + kb + k4 * 4]);
                cp16(Bd + so, &Bw[(size_t)m * K + kbase + k4 * 4]);
            }
        }
        cp_commit();   // uniform (possibly empty) group
    };

    auto compute = [&](int st) {
        const float* A  = Abuf + st * STAGEF;
        const float* Bs = Bbuf + st * STAGEF;
#pragma unroll
        for (int ks = 0; ks < 4; ks++) {
            uint32_t a[2][4];
#pragma unroll
            for (int mt = 0; mt < 2; mt++) {
                const float* ap = A + (wr * 32 + mt * 16 + g) * PADK + ks * 8 + tg;
                a[mt][0] = __float_as_uint(ap[0]);
                a[mt][1] = __float_as_uint(ap[8 * PADK]);
                a[mt][2] = __float_as_uint(ap[4]);
                a[mt][3] = __float_as_uint(ap[8 * PADK + 4]);
            }
#pragma unroll
            for (int nt = 0; nt < 8; nt++) {
                const float* bp = Bs + (wc * 64 + nt * 8 + g) * PADK + ks * 8 + tg;
                uint32_t b0 = __float_as_uint(bp[0]);
                uint32_t b1 = __float_as_uint(bp[4]);
                mma_tf32(acc[0][nt], a[0], b0, b1);
                mma_tf32(acc[1][nt], a[1], b0, b1);
            }
        }
    };

    issue(0);
    issue(1);
    for (int c = 0; c < NC; c++) {
        issue(c + 2);
        cp_wait2();               // group c complete
        __syncthreads();
        compute(c % NSTAGE);
        __syncthreads();          // protect stage before next issue overwrites
    }

    // epilogue
#pragma unroll
    for (int mt = 0; mt < 2; mt++) {
        int rb0 = m0 + wr * 32 + mt * 16 + g;
        float mk0 = 1.0f, mk1 = 1.0f;
        if (mask) {
            mk0 = mask[rb0] ? 1.0f : 0.0f;
            mk1 = mask[rb0 + 8] ? 1.0f : 0.0f;
        }
#pragma unroll
        for (int nt = 0; nt < 8; nt++) {
            int n = wc * 64 + nt * 8 + tg * 2;
            float b0 = bias[n], b1 = bias[n + 1];
            float v00 = acc[mt][nt][0] + b0, v01 = acc[mt][nt][1] + b1;
            float v10 = acc[mt][nt][2] + b0, v11 = acc[mt][nt][3] + b1;
            if (relu) {
                v00 = fmaxf(v00, 0.f); v01 = fmaxf(v01, 0.f);
                v10 = fmaxf(v10, 0.f); v11 = fmaxf(v11, 0.f);
            }
            v00 *= mk0; v01 *= mk0; v10 *= mk1; v11 *= mk1;
            if (round_out) {
                v00 = rtf(v00); v01 = rtf(v01); v10 = rtf(v10); v11 = rtf(v11);
            }
            *(float2*)&out[(size_t)rb0 * 128 + n] = make_float2(v00, v01);
            *(float2*)&out[(size_t)(rb0 + 8) * 128 + n] = make_float2(v10, v11);
        }
    }
}

// ---------------- launch ----------------------------------------------------
extern "C" void kernel_launch(void* const* d_in, const int* in_sizes, int n_in,
                              void* d_out, int out_size) {
    const int*   cid  = (const int*)  d_in[0];
    const int*   kid  = (const int*)  d_in[1];
    const int*   mask = (const int*)  d_in[2];
    const int*   eidx = (const int*)  d_in[3];
    const int*   et   = (const int*)  d_in[4];
    const float* ce   = (const float*)d_in[5];
    const float* ke   = (const float*)d_in[6];
    const float* pW   = (const float*)d_in[7];
    const float* pb   = (const float*)d_in[8];
    const float* sW   = (const float*)d_in[9];
    const float* sb   = (const float*)d_in[10];
    const float* rW   = (const float*)d_in[11];
    float* out = (float*)d_out;

    const int* esrc = eidx;
    const int* edst = eidx + NEDGE;

    float *x0p, *x1p, *Sp, *Wcp, *Wpp;
    cudaGetSymbolAddress((void**)&x0p, g_x0);
    cudaGetSymbolAddress((void**)&x1p, g_x1);
    cudaGetSymbolAddress((void**)&Sp,  g_S);
    cudaGetSymbolAddress((void**)&Wcp, (const void*)g_Wc);
    cudaGetSymbolAddress((void**)&Wpp, g_Wp);

    cudaFuncSetAttribute(mma_gemm_kernel,
                         cudaFuncAttributeMaxDynamicSharedMemorySize, GEMM_SMEM);

    // 1) CSR build
    zero_cnt_kernel<<<NODES / 256, 256>>>();
    hist_kernel<<<NEDGE / 256, 256>>>(edst);
    scan_kernel<<<1, 1024>>>();
    scatter_kernel<<<NEDGE / 256, 256>>>(esrc, edst, et);

    // 2) weights + embedding (tf32-rounded at producer)
    prep_w_kernel<<<1216, 256>>>(pW, sW, rW);
    embed_kernel<<<(NODES * 32) / 256, 256>>>(cid, kid, ce, ke);

    // 3) projection: x1 = x0 @ pW^T + pb   (round output: feeds agg + next GEMM)
    mma_gemm_kernel<<<NODES / 128, 256, GEMM_SMEM>>>(
        x0p, x0p, HDIM, HDIM, Wpp, pb, nullptr, 0, 1, x1p);

    // 4) layer 0
    agg_kernel<<<NODES / 8, 256>>>(x1p);
    mma_gemm_kernel<<<NODES / 128, 256, GEMM_SMEM>>>(
        x1p, Sp, HDIM, KTOT, Wcp, sb, nullptr, 1, 1, x0p);

    // 5) layer 1 (direct to output with mask, full-precision store)
    agg_kernel<<<NODES / 8, 256>>>(x0p);
    mma_gemm_kernel<<<NODES / 128, 256, GEMM_SMEM>>>(
        x0p, Sp, HDIM, KTOT, Wcp + (size_t)HDIM * KTOT, sb + HDIM, mask, 1, 0, out);
}

// round 10
// speedup vs baseline: 1.4645x; 1.0327x over previous
#include <cuda_runtime.h>
#include <cstdint>

// Problem constants
#define NODES   32768            // B*N = 8*4096
#define NEDGE   524288
#define HDIM    128
#define RNUM    8
#define LNUM    2
#define KTOT    (HDIM + RNUM*HDIM)   // 1152

// ---- GEMM tile params: 128x128 block, CHUNK=32, 3-stage cp.async ----
#define CHUNK   32
#define PADK    36
#define STAGEF  (128 * PADK)               // floats per A (or B) stage
#define NSTAGE  3
#define GEMM_SMEM (2 * NSTAGE * STAGEF * 4)  // 110592 B

// ---------------- scratch (static device globals; no allocation) ------------
__device__ float g_x0[(size_t)NODES * HDIM];
__device__ float g_x1[(size_t)NODES * HDIM];
__device__ float g_S [(size_t)NODES * RNUM * HDIM];          // 134 MB
__device__ float g_Wc[LNUM][(size_t)HDIM * KTOT];            // [l][n*KTOT + k]
__device__ float g_Wp[HDIM * HDIM];
__device__ int   g_rowptr[NODES + 1];
__device__ int   g_cursor[NODES];
__device__ float g_invdeg[NODES];
__device__ int   g_edges[NEDGE];                             // src | type<<16
__device__ int   g_cnt[NODES];

__device__ __forceinline__ uint32_t f2tf32(float v) {
    uint32_t r; asm("cvt.rna.tf32.f32 %0, %1;" : "=r"(r) : "f"(v)); return r;
}
__device__ __forceinline__ float rtf(float v) {
    return __uint_as_float(f2tf32(v));
}
__device__ __forceinline__ void mma_tf32(float* d, const uint32_t* a,
                                         uint32_t b0, uint32_t b1) {
    asm volatile(
        "mma.sync.aligned.m16n8k8.row.col.f32.tf32.tf32.f32 "
        "{%0,%1,%2,%3}, {%4,%5,%6,%7}, {%8,%9}, {%0,%1,%2,%3};"
        : "+f"(d[0]), "+f"(d[1]), "+f"(d[2]), "+f"(d[3])
        : "r"(a[0]), "r"(a[1]), "r"(a[2]), "r"(a[3]), "r"(b0), "r"(b1));
}
__device__ __forceinline__ uint32_t smem_u32(const void* p) {
    uint32_t a;
    asm("{ .reg .u64 t; cvta.to.shared.u64 t, %1; cvt.u32.u64 %0, t; }"
        : "=r"(a) : "l"(p));
    return a;
}
__device__ __forceinline__ void cp16(uint32_t dst, const float* src) {
    asm volatile("cp.async.cg.shared.global [%0], [%1], 16;"
                 :: "r"(dst), "l"(src) : "memory");
}
__device__ __forceinline__ void cp_commit() {
    asm volatile("cp.async.commit_group;" ::: "memory");
}
__device__ __forceinline__ void cp_wait2() {
    asm volatile("cp.async.wait_group 2;" ::: "memory");
}
// ldmatrix x4: lane mapping (row=l/4, f32col=l%4) == mma.sync tf32 frag layout
__device__ __forceinline__ void ldsm4(uint32_t* r, uint32_t addr) {
    asm volatile("ldmatrix.sync.aligned.m8n8.x4.shared.b16 {%0,%1,%2,%3}, [%4];"
                 : "=r"(r[0]), "=r"(r[1]), "=r"(r[2]), "=r"(r[3]) : "r"(addr));
}

// ---------------- CSR build (per dst) ---------------------------------------
__global__ void zero_cnt_kernel() {
    int i = blockIdx.x * blockDim.x + threadIdx.x;
    if (i < NODES) g_cnt[i] = 0;
}
__global__ void hist_kernel(const int* __restrict__ dst) {
    int i = blockIdx.x * blockDim.x + threadIdx.x;
    if (i < NEDGE) atomicAdd(&g_cnt[dst[i]], 1);
}
__global__ void scan_kernel() {
    __shared__ int sh[1024];
    int t = threadIdx.x;
    int base = t * 32;
    int local[32];
    int sum = 0;
#pragma unroll
    for (int i = 0; i < 32; i++) { local[i] = g_cnt[base + i]; sum += local[i]; }
    sh[t] = sum;
    __syncthreads();
    for (int off = 1; off < 1024; off <<= 1) {
        int v = (t >= off) ? sh[t - off] : 0;
        __syncthreads();
        sh[t] += v;
        __syncthreads();
    }
    int run = sh[t] - sum;
#pragma unroll
    for (int i = 0; i < 32; i++) {
        g_rowptr[base + i] = run;
        g_cursor[base + i] = run;
        g_invdeg[base + i] = 1.0f / (float)max(local[i], 1);
        run += local[i];
    }
    if (t == 1023) g_rowptr[NODES] = run;
}
__global__ void scatter_kernel(const int* __restrict__ src,
                               const int* __restrict__ dst,
                               const int* __restrict__ et) {
    int i = blockIdx.x * blockDim.x + threadIdx.x;
    if (i < NEDGE) {
        int d = dst[i];
        int pos = atomicAdd(&g_cursor[d], 1);
        g_edges[pos] = (src[i] & 0xFFFF) | (et[i] << 16);
    }
}

// ------- weight prep (tf32-rounded): Wc = [self | rel], Wp = proj_W ---------
__global__ void prep_w_kernel(const float* __restrict__ pW,
                              const float* __restrict__ sW,
                              const float* __restrict__ rW) {
    const int total = HDIM * HDIM + LNUM * HDIM * KTOT;
    for (int idx = blockIdx.x * blockDim.x + threadIdx.x; idx < total;
         idx += gridDim.x * blockDim.x) {
        if (idx < HDIM * HDIM) {
            g_Wp[idx] = rtf(pW[idx]);            // [g][h] as-is (B is N x K)
        } else {
            int j  = idx - HDIM * HDIM;
            int l  = j / (HDIM * KTOT);
            int jj = j % (HDIM * KTOT);
            int n  = jj / KTOT, k = jj % KTOT;
            float v;
            if (k < HDIM) {
                v = sW[((size_t)l * HDIM + n) * HDIM + k];
            } else {
                int kk = k - HDIM;
                int r = kk >> 7, h = kk & 127;
                v = rW[(((size_t)(l * RNUM + r) * HDIM) + n) * HDIM + h];
            }
            g_Wc[l][jj] = rtf(v);
        }
    }
}

// ---------------- embedding (tf32-rounded) ----------------------------------
__global__ void embed_kernel(const int* __restrict__ cid,
                             const int* __restrict__ kid,
                             const float* __restrict__ ce,
                             const float* __restrict__ ke) {
    int i = blockIdx.x * blockDim.x + threadIdx.x;
    int v = i >> 5, j = i & 31;
    float4 a = ((const float4*)ce)[(size_t)cid[v] * 32 + j];
    float4 b = ((const float4*)ke)[(size_t)kid[v] * 32 + j];
    float4 o;
    o.x = rtf(a.x + b.x); o.y = rtf(a.y + b.y);
    o.z = rtf(a.z + b.z); o.w = rtf(a.w + b.w);
    ((float4*)g_x0)[(size_t)v * 32 + j] = o;
}

// ---------------- aggregation: one warp per dst node (S tf32-rounded) -------
__global__ void agg_kernel(const float* __restrict__ x) {
    int warp = (blockIdx.x * blockDim.x + threadIdx.x) >> 5;
    int lane = threadIdx.x & 31;
    int v = warp;
    int s = g_rowptr[v], e = g_rowptr[v + 1];
    float4 acc[RNUM];
#pragma unroll
    for (int r = 0; r < RNUM; r++) acc[r] = make_float4(0.f, 0.f, 0.f, 0.f);
    const float4* x4 = (const float4*)x;
    for (int i = s; i < e; i++) {
        int p   = g_edges[i];
        int src = p & 0xFFFF;
        int r   = p >> 16;
        float4 xv = x4[(size_t)src * 32 + lane];
        switch (r) {
            case 0: acc[0].x += xv.x; acc[0].y += xv.y; acc[0].z += xv.z; acc[0].w += xv.w; break;
            case 1: acc[1].x += xv.x; acc[1].y += xv.y; acc[1].z += xv.z; acc[1].w += xv.w; break;
            case 2: acc[2].x += xv.x; acc[2].y += xv.y; acc[2].z += xv.z; acc[2].w += xv.w; break;
            case 3: acc[3].x += xv.x; acc[3].y += xv.y; acc[3].z += xv.z; acc[3].w += xv.w; break;
            case 4: acc[4].x += xv.x; acc[4].y += xv.y; acc[4].z += xv.z; acc[4].w += xv.w; break;
            case 5: acc[5].x += xv.x; acc[5].y += xv.y; acc[5].z += xv.z; acc[5].w += xv.w; break;
            case 6: acc[6].x += xv.x; acc[6].y += xv.y; acc[6].z += xv.z; acc[6].w += xv.w; break;
            default: acc[7].x += xv.x; acc[7].y += xv.y; acc[7].z += xv.z; acc[7].w += xv.w; break;
        }
    }
    float inv = g_invdeg[v];
    float4* S4 = (float4*)g_S;
#pragma unroll
    for (int r = 0; r < RNUM; r++) {
        float4 o;
        o.x = rtf(acc[r].x * inv); o.y = rtf(acc[r].y * inv);
        o.z = rtf(acc[r].z * inv); o.w = rtf(acc[r].w * inv);
        S4[((size_t)v * RNUM + r) * 32 + lane] = o;
    }
}

// ====== tf32 mma GEMM: cp.async 3-stage + ldmatrix fragment loads ===========
// A_cat rows: cols [0,K1) from A1 (lda=K1), [K1,K) from A2 (lda=K-K1).
// B: [128 n][K k] K-major, pre-rounded tf32.
__global__ __launch_bounds__(256, 2)
void mma_gemm_kernel(const float* __restrict__ A1, const float* __restrict__ A2,
                     int K1, int K, const float* __restrict__ Bw,
                     const float* __restrict__ bias, const int* __restrict__ mask,
                     int relu, int round_out, float* __restrict__ out) {
    extern __shared__ float sm[];
    float* Abuf = sm;                      // [NSTAGE][STAGEF]
    float* Bbuf = sm + NSTAGE * STAGEF;    // [NSTAGE][STAGEF]
    uint32_t Abase = smem_u32(Abuf);
    uint32_t Bbase = smem_u32(Bbuf);

    int tid = threadIdx.x, wid = tid >> 5, lane = tid & 31;
    int m0 = blockIdx.x * 128;
    int wr = wid & 3, wc = wid >> 2;
    int g = lane >> 2, tg = lane & 3;

    // per-lane ldmatrix row-pointer offsets (bytes)
    // A: quad bit0 (lane>>3 &1) -> +8 rows, quad bit1 (lane>>4) -> +4 k
    uint32_t aoff = ((((lane & 7) + ((lane >> 3) & 1) * 8) * PADK)
                     + ((lane >> 4) & 1) * 4) * 4;
    // B: quad bit1 -> +8 n rows, quad bit0 -> +4 k
    uint32_t boff = ((((lane & 7) + ((lane >> 4) & 1) * 8) * PADK)
                     + ((lane >> 3) & 1) * 4) * 4;
    uint32_t aRowA = (uint32_t)(wr * 32) * PADK * 4;        // warp A row base
    uint32_t bRowB = (uint32_t)(wc * 64) * PADK * 4;        // warp B row base

    float acc[2][8][4];
#pragma unroll
    for (int mt = 0; mt < 2; mt++)
#pragma unroll
        for (int nt = 0; nt < 8; nt++)
#pragma unroll
            for (int r = 0; r < 4; r++) acc[mt][nt][r] = 0.f;

    const int NC = K / CHUNK;

    auto issue = [&](int c) {
        if (c < NC) {
            int kbase = c * CHUNK;
            const float* Aq; int lda, kb;
            if (kbase < K1) { Aq = A1; lda = K1;     kb = kbase; }
            else            { Aq = A2; lda = K - K1; kb = kbase - K1; }
            int st = c % NSTAGE;
            uint32_t Ad = Abase + st * STAGEF * 4;
            uint32_t Bd = Bbase + st * STAGEF * 4;
#pragma unroll
            for (int i = 0; i < 4; i++) {
                int idx = i * 256 + tid;          // 1024 f4 per tile
                int m = idx >> 3, k4 = idx & 7;
                uint32_t so = (uint32_t)(m * PADK + k4 * 4) * 4;
                cp16(Ad + so, &Aq[(size_t)(m0 + m) * lda + kb + k4 * 4]);
                cp16(Bd + so, &Bw[(size_t)m * K + kbase + k4 * 4]);
            }
        }
        cp_commit();   // uniform (possibly empty) group
    };

    auto compute = [&](int st) {
        uint32_t Au = Abase + st * STAGEF * 4 + aRowA + aoff;
        uint32_t Bu = Bbase + st * STAGEF * 4 + bRowB + boff;
#pragma unroll
        for (int ks = 0; ks < 4; ks++) {
            uint32_t kb = (uint32_t)ks * 32;           // ks*8 floats
            uint32_t a[2][4];
            ldsm4(a[0], Au + kb);
            ldsm4(a[1], Au + (uint32_t)(16 * PADK * 4) + kb);
#pragma unroll
            for (int p = 0; p < 4; p++) {              // nt pair {2p, 2p+1}
                uint32_t rb[4];
                ldsm4(rb, Bu + (uint32_t)(p * 16 * PADK * 4) + kb);
                mma_tf32(acc[0][2 * p],     a[0], rb[0], rb[1]);
                mma_tf32(acc[1][2 * p],     a[1], rb[0], rb[1]);
                mma_tf32(acc[0][2 * p + 1], a[0], rb[2], rb[3]);
                mma_tf32(acc[1][2 * p + 1], a[1], rb[2], rb[3]);
            }
        }
    };

    issue(0);
    issue(1);
    for (int c = 0; c < NC; c++) {
        issue(c + 2);
        cp_wait2();               // group c complete
        __syncthreads();
        compute(c % NSTAGE);
        __syncthreads();          // protect stage before next issue overwrites
    }

    // epilogue
#pragma unroll
    for (int mt = 0; mt < 2; mt++) {
        int rb0 = m0 + wr * 32 + mt * 16 + g;
        float mk0 = 1.0f, mk1 = 1.0f;
        if (mask) {
            mk0 = mask[rb0] ? 1.0f : 0.0f;
            mk1 = mask[rb0 + 8] ? 1.0f : 0.0f;
        }
#pragma unroll
        for (int nt = 0; nt < 8; nt++) {
            int n = wc * 64 + nt * 8 + tg * 2;
            float b0 = bias[n], b1 = bias[n + 1];
            float v00 = acc[mt][nt][0] + b0, v01 = acc[mt][nt][1] + b1;
            float v10 = acc[mt][nt][2] + b0, v11 = acc[mt][nt][3] + b1;
            if (relu) {
                v00 = fmaxf(v00, 0.f); v01 = fmaxf(v01, 0.f);
                v10 = fmaxf(v10, 0.f); v11 = fmaxf(v11, 0.f);
            }
            v00 *= mk0; v01 *= mk0; v10 *= mk1; v11 *= mk1;
            if (round_out) {
                v00 = rtf(v00); v01 = rtf(v01); v10 = rtf(v10); v11 = rtf(v11);
            }
            *(float2*)&out[(size_t)rb0 * 128 + n] = make_float2(v00, v01);
            *(float2*)&out[(size_t)(rb0 + 8) * 128 + n] = make_float2(v10, v11);
        }
    }
}

// ---------------- launch ----------------------------------------------------
extern "C" void kernel_launch(void* const* d_in, const int* in_sizes, int n_in,
                              void* d_out, int out_size) {
    const int*   cid  = (const int*)  d_in[0];
    const int*   kid  = (const int*)  d_in[1];
    const int*   mask = (const int*)  d_in[2];
    const int*   eidx = (const int*)  d_in[3];
    const int*   et   = (const int*)  d_in[4];
    const float* ce   = (const float*)d_in[5];
    const float* ke   = (const float*)d_in[6];
    const float* pW   = (const float*)d_in[7];
    const float* pb   = (const float*)d_in[8];
    const float* sW   = (const float*)d_in[9];
    const float* sb   = (const float*)d_in[10];
    const float* rW   = (const float*)d_in[11];
    float* out = (float*)d_out;

    const int* esrc = eidx;
    const int* edst = eidx + NEDGE;

    float *x0p, *x1p, *Sp, *Wcp, *Wpp;
    cudaGetSymbolAddress((void**)&x0p, g_x0);
    cudaGetSymbolAddress((void**)&x1p, g_x1);
    cudaGetSymbolAddress((void**)&Sp,  g_S);
    cudaGetSymbolAddress((void**)&Wcp, (const void*)g_Wc);
    cudaGetSymbolAddress((void**)&Wpp, g_Wp);

    cudaFuncSetAttribute(mma_gemm_kernel,
                         cudaFuncAttributeMaxDynamicSharedMemorySize, GEMM_SMEM);

    // 1) CSR build
    zero_cnt_kernel<<<NODES / 256, 256>>>();
    hist_kernel<<<NEDGE / 256, 256>>>(edst);
    scan_kernel<<<1, 1024>>>();
    scatter_kernel<<<NEDGE / 256, 256>>>(esrc, edst, et);

    // 2) weights + embedding (tf32-rounded at producer)
    prep_w_kernel<<<1216, 256>>>(pW, sW, rW);
    embed_kernel<<<(NODES * 32) / 256, 256>>>(cid, kid, ce, ke);

    // 3) projection: x1 = x0 @ pW^T + pb   (round output: feeds agg + next GEMM)
    mma_gemm_kernel<<<NODES / 128, 256, GEMM_SMEM>>>(
        x0p, x0p, HDIM, HDIM, Wpp, pb, nullptr, 0, 1, x1p);

    // 4) layer 0
    agg_kernel<<<NODES / 8, 256>>>(x1p);
    mma_gemm_kernel<<<NODES / 128, 256, GEMM_SMEM>>>(
        x1p, Sp, HDIM, KTOT, Wcp, sb, nullptr, 1, 1, x0p);

    // 5) layer 1 (direct to output with mask, full-precision store)
    agg_kernel<<<NODES / 8, 256>>>(x0p);
    mma_gemm_kernel<<<NODES / 128, 256, GEMM_SMEM>>>(
        x0p, Sp, HDIM, KTOT, Wcp + (size_t)HDIM * KTOT, sb + HDIM, mask, 1, 0, out);
}

// round 16
// speedup vs baseline: 1.7468x; 1.1928x over previous
#include <cuda_runtime.h>
#include <cuda_fp16.h>
#include <cstdint>

// Problem constants
#define NODES   32768            // B*N = 8*4096
#define NEDGE   524288
#define HDIM    128
#define RNUM    8
#define LNUM    2
#define KTOT    (HDIM + RNUM*HDIM)   // 1152

// ---- GEMM tile params: 128x128 block, 64-half chunks, 3-stage cp.async ----
#define CHUNKH  64                         // halves of K per stage
#define PADH    72                         // smem row stride in halves
#define STAGEH  (128 * PADH)               // halves per A (or B) stage
#define NSTAGE  3
#define GEMM_SMEM (2 * NSTAGE * STAGEH * 2)  // 110592 B

// ---------------- scratch (static device globals; no allocation) ------------
__device__ __half g_x0[(size_t)NODES * HDIM];                // 8.4 MB
__device__ __half g_x1[(size_t)NODES * HDIM];                // 8.4 MB
__device__ __half g_S [(size_t)NODES * RNUM * HDIM];         // 67 MB
__device__ __half g_Wc[LNUM][(size_t)HDIM * KTOT];           // [l][n*KTOT + k]
__device__ __half g_Wp[HDIM * HDIM];
__device__ int    g_rowptr[NODES + 1];
__device__ int    g_cursor[NODES];
__device__ float  g_invdeg[NODES];
__device__ int    g_edges[NEDGE];                            // src | type<<16
__device__ int    g_cnt[NODES];

__device__ __forceinline__ void mma_f16(float* d, const uint32_t* a,
                                        uint32_t b0, uint32_t b1) {
    asm volatile(
        "mma.sync.aligned.m16n8k16.row.col.f32.f16.f16.f32 "
        "{%0,%1,%2,%3}, {%4,%5,%6,%7}, {%8,%9}, {%0,%1,%2,%3};"
        : "+f"(d[0]), "+f"(d[1]), "+f"(d[2]), "+f"(d[3])
        : "r"(a[0]), "r"(a[1]), "r"(a[2]), "r"(a[3]), "r"(b0), "r"(b1));
}
__device__ __forceinline__ uint32_t smem_u32(const void* p) {
    uint32_t a;
    asm("{ .reg .u64 t; cvta.to.shared.u64 t, %1; cvt.u32.u64 %0, t; }"
        : "=r"(a) : "l"(p));
    return a;
}
__device__ __forceinline__ void cp16(uint32_t dst, const void* src) {
    asm volatile("cp.async.cg.shared.global [%0], [%1], 16;"
                 :: "r"(dst), "l"(src) : "memory");
}
__device__ __forceinline__ void cp_commit() {
    asm volatile("cp.async.commit_group;" ::: "memory");
}
__device__ __forceinline__ void cp_wait2() {
    asm volatile("cp.async.wait_group 2;" ::: "memory");
}
__device__ __forceinline__ void ldsm4(uint32_t* r, uint32_t addr) {
    asm volatile("ldmatrix.sync.aligned.m8n8.x4.shared.b16 {%0,%1,%2,%3}, [%4];"
                 : "=r"(r[0]), "=r"(r[1]), "=r"(r[2]), "=r"(r[3]) : "r"(addr));
}

// ---------------- CSR build (per dst) ---------------------------------------
__global__ void zero_cnt_kernel() {
    int i = blockIdx.x * blockDim.x + threadIdx.x;
    if (i < NODES) g_cnt[i] = 0;
}
__global__ void hist_kernel(const int* __restrict__ dst) {
    int i = blockIdx.x * blockDim.x + threadIdx.x;
    if (i < NEDGE) atomicAdd(&g_cnt[dst[i]], 1);
}
__global__ void scan_kernel() {
    __shared__ int sh[1024];
    int t = threadIdx.x;
    int base = t * 32;
    int local[32];
    int sum = 0;
#pragma unroll
    for (int i = 0; i < 32; i++) { local[i] = g_cnt[base + i]; sum += local[i]; }
    sh[t] = sum;
    __syncthreads();
    for (int off = 1; off < 1024; off <<= 1) {
        int v = (t >= off) ? sh[t - off] : 0;
        __syncthreads();
        sh[t] += v;
        __syncthreads();
    }
    int run = sh[t] - sum;
#pragma unroll
    for (int i = 0; i < 32; i++) {
        g_rowptr[base + i] = run;
        g_cursor[base + i] = run;
        g_invdeg[base + i] = 1.0f / (float)max(local[i], 1);
        run += local[i];
    }
    if (t == 1023) g_rowptr[NODES] = run;
}
__global__ void scatter_kernel(const int* __restrict__ src,
                               const int* __restrict__ dst,
                               const int* __restrict__ et) {
    int i = blockIdx.x * blockDim.x + threadIdx.x;
    if (i < NEDGE) {
        int d = dst[i];
        int pos = atomicAdd(&g_cursor[d], 1);
        g_edges[pos] = (src[i] & 0xFFFF) | (et[i] << 16);
    }
}

// ------- weight prep (fp16-rounded): Wc = [self | rel], Wp = proj_W ---------
__global__ void prep_w_kernel(const float* __restrict__ pW,
                              const float* __restrict__ sW,
                              const float* __restrict__ rW) {
    const int total = HDIM * HDIM + LNUM * HDIM * KTOT;
    for (int idx = blockIdx.x * blockDim.x + threadIdx.x; idx < total;
         idx += gridDim.x * blockDim.x) {
        if (idx < HDIM * HDIM) {
            g_Wp[idx] = __float2half_rn(pW[idx]);   // [g][h] as-is (B is N x K)
        } else {
            int j  = idx - HDIM * HDIM;
            int l  = j / (HDIM * KTOT);
            int jj = j % (HDIM * KTOT);
            int n  = jj / KTOT, k = jj % KTOT;
            float v;
            if (k < HDIM) {
                v = sW[((size_t)l * HDIM + n) * HDIM + k];
            } else {
                int kk = k - HDIM;
                int r = kk >> 7, h = kk & 127;
                v = rW[(((size_t)(l * RNUM + r) * HDIM) + n) * HDIM + h];
            }
            g_Wc[l][jj] = __float2half_rn(v);
        }
    }
}

// ---------------- embedding (fp16-rounded) ----------------------------------
__global__ void embed_kernel(const int* __restrict__ cid,
                             const int* __restrict__ kid,
                             const float* __restrict__ ce,
                             const float* __restrict__ ke) {
    int i = blockIdx.x * blockDim.x + threadIdx.x;   // NODES*32 units of 4
    int v = i >> 5, j = i & 31;
    float4 a = ((const float4*)ce)[(size_t)cid[v] * 32 + j];
    float4 b = ((const float4*)ke)[(size_t)kid[v] * 32 + j];
    __half2 h0 = __floats2half2_rn(a.x + b.x, a.y + b.y);
    __half2 h1 = __floats2half2_rn(a.z + b.z, a.w + b.w);
    uint2 o;
    o.x = *(uint32_t*)&h0;
    o.y = *(uint32_t*)&h1;
    ((uint2*)g_x0)[(size_t)v * 32 + j] = o;
}

// ---------------- aggregation: one warp per dst node (S fp16) ---------------
// each lane owns 4 half features (8 bytes) of the 128-half row
__global__ void agg_kernel(const __half* __restrict__ x) {
    int warp = (blockIdx.x * blockDim.x + threadIdx.x) >> 5;
    int lane = threadIdx.x & 31;
    int v = warp;
    int s = g_rowptr[v], e = g_rowptr[v + 1];
    float4 acc[RNUM];
#pragma unroll
    for (int r = 0; r < RNUM; r++) acc[r] = make_float4(0.f, 0.f, 0.f, 0.f);
    const uint2* x2 = (const uint2*)x;               // 32 uint2 per row
    for (int i = s; i < e; i++) {
        int p   = g_edges[i];
        int src = p & 0xFFFF;
        int r   = p >> 16;
        uint2 w = x2[(size_t)src * 32 + lane];
        __half2 h0 = *(__half2*)&w.x;
        __half2 h1 = *(__half2*)&w.y;
        float2 f0 = __half22float2(h0);
        float2 f1 = __half22float2(h1);
        switch (r) {
            case 0: acc[0].x += f0.x; acc[0].y += f0.y; acc[0].z += f1.x; acc[0].w += f1.y; break;
            case 1: acc[1].x += f0.x; acc[1].y += f0.y; acc[1].z += f1.x; acc[1].w += f1.y; break;
            case 2: acc[2].x += f0.x; acc[2].y += f0.y; acc[2].z += f1.x; acc[2].w += f1.y; break;
            case 3: acc[3].x += f0.x; acc[3].y += f0.y; acc[3].z += f1.x; acc[3].w += f1.y; break;
            case 4: acc[4].x += f0.x; acc[4].y += f0.y; acc[4].z += f1.x; acc[4].w += f1.y; break;
            case 5: acc[5].x += f0.x; acc[5].y += f0.y; acc[5].z += f1.x; acc[5].w += f1.y; break;
            case 6: acc[6].x += f0.x; acc[6].y += f0.y; acc[6].z += f1.x; acc[6].w += f1.y; break;
            default: acc[7].x += f0.x; acc[7].y += f0.y; acc[7].z += f1.x; acc[7].w += f1.y; break;
        }
    }
    float inv = g_invdeg[v];
    uint2* S2 = (uint2*)g_S;
#pragma unroll
    for (int r = 0; r < RNUM; r++) {
        __half2 h0 = __floats2half2_rn(acc[r].x * inv, acc[r].y * inv);
        __half2 h1 = __floats2half2_rn(acc[r].z * inv, acc[r].w * inv);
        uint2 o;
        o.x = *(uint32_t*)&h0;
        o.y = *(uint32_t*)&h1;
        // half offset: v*1024 + r*128 + lane*4  -> uint2 index /4
        S2[(((size_t)v * RNUM + r) * 128 + lane * 4) >> 2] = o;
    }
}

// ====== fp16 mma GEMM: cp.async 3-stage + ldmatrix b16 ======================
// A_cat rows: cols [0,K1) from A1 (lda=K1), [K1,K) from A2 (lda=K-K1), halves.
// B: [128 n][K k] K-major fp16. out: half (outh) or float (outf).
__global__ __launch_bounds__(256, 2)
void mma_gemm_kernel(const __half* __restrict__ A1, const __half* __restrict__ A2,
                     int K1, int K, const __half* __restrict__ Bw,
                     const float* __restrict__ bias, const int* __restrict__ mask,
                     int relu, __half* __restrict__ outh, float* __restrict__ outf) {
    extern __shared__ __half smh[];
    __half* Abuf = smh;                      // [NSTAGE][STAGEH]
    __half* Bbuf = smh + NSTAGE * STAGEH;    // [NSTAGE][STAGEH]
    uint32_t Abase = smem_u32(Abuf);
    uint32_t Bbase = smem_u32(Bbuf);

    int tid = threadIdx.x, wid = tid >> 5, lane = tid & 31;
    int m0 = blockIdx.x * 128;
    int wr = wid & 3, wc = wid >> 2;
    int g = lane >> 2, tg = lane & 3;

    // ldmatrix per-lane row pointers (bytes)
    // A (m16k16): lanes 0-7 m0-7/k0, 8-15 m8-15/k0, 16-23 m0-7/k8, 24-31 m8-15/k8
    uint32_t aoff = ((uint32_t)(((lane & 7) + ((lane >> 3) & 1) * 8) * PADH)
                     + ((lane >> 4) & 1) * 8) * 2;
    // B (n8k16 x2 tiles): lanes 0-7 n0-7/k0, 8-15 n0-7/k8, 16-23 n8-15/k0, 24-31 n8-15/k8
    uint32_t boff = ((uint32_t)(((lane & 7) + ((lane >> 4) & 1) * 8) * PADH)
                     + ((lane >> 3) & 1) * 8) * 2;
    uint32_t aRow = (uint32_t)(wr * 32) * PADH * 2;
    uint32_t bRow = (uint32_t)(wc * 64) * PADH * 2;

    float acc[2][8][4];
#pragma unroll
    for (int mt = 0; mt < 2; mt++)
#pragma unroll
        for (int nt = 0; nt < 8; nt++)
#pragma unroll
            for (int r = 0; r < 4; r++) acc[mt][nt][r] = 0.f;

    const int NC = K / CHUNKH;

    auto issue = [&](int c) {
        if (c < NC) {
            int kbase = c * CHUNKH;
            const __half* Aq; int lda, kb;
            if (kbase < K1) { Aq = A1; lda = K1;     kb = kbase; }
            else            { Aq = A2; lda = K - K1; kb = kbase - K1; }
            int st = c % NSTAGE;
            uint32_t Ad = Abase + st * STAGEH * 2;
            uint32_t Bd = Bbase + st * STAGEH * 2;
#pragma unroll
            for (int i = 0; i < 4; i++) {
                int idx = i * 256 + tid;          // 1024 16B-units per tile
                int m = idx >> 3, k8 = idx & 7;   // row, 8-half unit
                uint32_t so = (uint32_t)(m * PADH + k8 * 8) * 2;
                cp16(Ad + so, &Aq[(size_t)(m0 + m) * lda + kb + k8 * 8]);
                cp16(Bd + so, &Bw[(size_t)m * K + kbase + k8 * 8]);
            }
        }
        cp_commit();   // uniform (possibly empty) group
    };

    auto compute = [&](int st) {
        uint32_t Au = Abase + st * STAGEH * 2 + aRow + aoff;
        uint32_t Bu = Bbase + st * STAGEH * 2 + bRow + boff;
#pragma unroll
        for (int ks = 0; ks < 4; ks++) {              // K = 4 x 16
            uint32_t kb = (uint32_t)ks * 32;          // 16 halves = 32 B
            uint32_t a[2][4];
            ldsm4(a[0], Au + kb);
            ldsm4(a[1], Au + (uint32_t)(16 * PADH * 2) + kb);
#pragma unroll
            for (int p = 0; p < 4; p++) {             // nt pair {2p, 2p+1}
                uint32_t rb[4];
                ldsm4(rb, Bu + (uint32_t)(p * 16 * PADH * 2) + kb);
                mma_f16(acc[0][2 * p],     a[0], rb[0], rb[1]);
                mma_f16(acc[1][2 * p],     a[1], rb[0], rb[1]);
                mma_f16(acc[0][2 * p + 1], a[0], rb[2], rb[3]);
                mma_f16(acc[1][2 * p + 1], a[1], rb[2], rb[3]);
            }
        }
    };

    issue(0);
    issue(1);
    for (int c = 0; c < NC; c++) {
        issue(c + 2);
        cp_wait2();
        __syncthreads();
        compute(c % NSTAGE);
        __syncthreads();
    }

    // epilogue
#pragma unroll
    for (int mt = 0; mt < 2; mt++) {
        int rb0 = m0 + wr * 32 + mt * 16 + g;
        float mk0 = 1.0f, mk1 = 1.0f;
        if (mask) {
            mk0 = mask[rb0] ? 1.0f : 0.0f;
            mk1 = mask[rb0 + 8] ? 1.0f : 0.0f;
        }
#pragma unroll
        for (int nt = 0; nt < 8; nt++) {
            int n = wc * 64 + nt * 8 + tg * 2;
            float b0 = bias[n], b1 = bias[n + 1];
            float v00 = acc[mt][nt][0] + b0, v01 = acc[mt][nt][1] + b1;
            float v10 = acc[mt][nt][2] + b0, v11 = acc[mt][nt][3] + b1;
            if (relu) {
                v00 = fmaxf(v00, 0.f); v01 = fmaxf(v01, 0.f);
                v10 = fmaxf(v10, 0.f); v11 = fmaxf(v11, 0.f);
            }
            v00 *= mk0; v01 *= mk0; v10 *= mk1; v11 *= mk1;
            if (outh) {
                __half2 h0 = __floats2half2_rn(v00, v01);
                __half2 h1 = __floats2half2_rn(v10, v11);
                *(uint32_t*)&outh[(size_t)rb0 * 128 + n] = *(uint32_t*)&h0;
                *(uint32_t*)&outh[(size_t)(rb0 + 8) * 128 + n] = *(uint32_t*)&h1;
            } else {
                *(float2*)&outf[(size_t)rb0 * 128 + n] = make_float2(v00, v01);
                *(float2*)&outf[(size_t)(rb0 + 8) * 128 + n] = make_float2(v10, v11);
            }
        }
    }
}

// ---------------- launch ----------------------------------------------------
extern "C" void kernel_launch(void* const* d_in, const int* in_sizes, int n_in,
                              void* d_out, int out_size) {
    const int*   cid  = (const int*)  d_in[0];
    const int*   kid  = (const int*)  d_in[1];
    const int*   mask = (const int*)  d_in[2];
    const int*   eidx = (const int*)  d_in[3];
    const int*   et   = (const int*)  d_in[4];
    const float* ce   = (const float*)d_in[5];
    const float* ke   = (const float*)d_in[6];
    const float* pW   = (const float*)d_in[7];
    const float* pb   = (const float*)d_in[8];
    const float* sW   = (const float*)d_in[9];
    const float* sb   = (const float*)d_in[10];
    const float* rW   = (const float*)d_in[11];
    float* out = (float*)d_out;

    const int* esrc = eidx;
    const int* edst = eidx + NEDGE;

    __half *x0p, *x1p, *Sp, *Wcp, *Wpp;
    cudaGetSymbolAddress((void**)&x0p, g_x0);
    cudaGetSymbolAddress((void**)&x1p, g_x1);
    cudaGetSymbolAddress((void**)&Sp,  g_S);
    cudaGetSymbolAddress((void**)&Wcp, (const void*)g_Wc);
    cudaGetSymbolAddress((void**)&Wpp, g_Wp);

    cudaFuncSetAttribute(mma_gemm_kernel,
                         cudaFuncAttributeMaxDynamicSharedMemorySize, GEMM_SMEM);

    // 1) CSR build
    zero_cnt_kernel<<<NODES / 256, 256>>>();
    hist_kernel<<<NEDGE / 256, 256>>>(edst);
    scan_kernel<<<1, 1024>>>();
    scatter_kernel<<<NEDGE / 256, 256>>>(esrc, edst, et);

    // 2) weights + embedding (fp16-rounded at producer)
    prep_w_kernel<<<1216, 256>>>(pW, sW, rW);
    embed_kernel<<<(NODES * 32) / 256, 256>>>(cid, kid, ce, ke);

    // 3) projection: x1 = x0 @ pW^T + pb  (half out: feeds agg + next GEMM)
    mma_gemm_kernel<<<NODES / 128, 256, GEMM_SMEM>>>(
        x0p, x0p, HDIM, HDIM, Wpp, pb, nullptr, 0, x1p, nullptr);

    // 4) layer 0
    agg_kernel<<<NODES / 8, 256>>>(x1p);
    mma_gemm_kernel<<<NODES / 128, 256, GEMM_SMEM>>>(
        x1p, Sp, HDIM, KTOT, Wcp, sb, nullptr, 1, x0p, nullptr);

    // 5) layer 1 (direct to float output with mask)
    agg_kernel<<<NODES / 8, 256>>>(x0p);
    mma_gemm_kernel<<<NODES / 128, 256, GEMM_SMEM>>>(
        x0p, Sp, HDIM, KTOT, Wcp + (size_t)HDIM * KTOT, sb + HDIM, mask, 1,
        nullptr, out);
}